// round 9
// baseline (speedup 1.0000x reference)
#include <cuda_runtime.h>
#include <cstdint>

#define NPIX 262144      // 512*512
#define C64  64
#define LBL  8
#define NBLK 128         // hist blocks per side, 2048 px each
#define S2CHUNK 16
#define APCHUNK 32
#define NSIT 7
#define PADPIX (NPIX + 512)

// ---------------- static device scratch (allocations are forbidden) -------
__device__ int   g_blockcnt[2][NBLK][LBL];
__device__ int   g_base[2][NBLK][LBL];
__device__ int   g_boffA[2][LBL + 1];            // 64-aligned bucket starts
__device__ int   g_cnt[2][LBL];                  // actual bucket sizes
__device__ __align__(16) int   g_idx[2][PADPIX]; // bucket pos -> pixel index
__device__ __align__(16) int   g_pos[2][NPIX];   // pixel index -> bucket pos
__device__ __align__(16) float g_packed[2][C64][PADPIX];
__device__ float g_pS2[2][LBL][S2CHUNK][C64 * C64];
__device__ float g_psum[2][LBL][S2CHUNK][C64];
__device__ float g_cov[2][LBL][C64 * C64];
__device__ float g_mu[2][LBL][C64];
__device__ float g_M[2][LBL][C64 * C64];  // side0: (cov_c+I)^-1/2, side1: cov_s^1/2
__device__ float g_T[LBL][C64 * C64];
__device__ float g_bias[LBL][C64];

// ---------------- packed f32x2 helpers ------------------------------------
__device__ __forceinline__ unsigned long long pk2(float lo, float hi) {
    unsigned long long r;
    asm("mov.b64 %0, {%1, %2};" : "=l"(r) : "f"(lo), "f"(hi));
    return r;
}
__device__ __forceinline__ void fma2(unsigned long long& d,
                                     unsigned long long a,
                                     unsigned long long b) {
    asm("fma.rn.f32x2 %0, %1, %2, %0;" : "+l"(d) : "l"(a), "l"(b));
}
__device__ __forceinline__ float2 upk(unsigned long long v) {
    float2 f;
    asm("mov.b64 {%0, %1}, %2;" : "=f"(f.x), "=f"(f.y) : "l"(v));
    return f;
}

// ---------------- 1. per-block label histograms ---------------------------
__global__ void k_hist(const int* __restrict__ cseg, const int* __restrict__ sseg) {
    int side = blockIdx.y;
    const int* seg = side ? sseg : cseg;
    int t = threadIdx.x;
    __shared__ int sc[LBL];
    if (t < LBL) sc[t] = 0;
    __syncthreads();
    int base = blockIdx.x * 2048 + t * 8;
    int lc[LBL] = {0, 0, 0, 0, 0, 0, 0, 0};
#pragma unroll
    for (int j = 0; j < 8; j++) { int l = seg[base + j] & 7; lc[l]++; }
#pragma unroll
    for (int l = 0; l < LBL; l++)
        if (lc[l]) atomicAdd(&sc[l], lc[l]);
    __syncthreads();
    if (t < LBL) g_blockcnt[side][blockIdx.x][t] = sc[t];
}

// ---------------- 2. scans (tiny, 1 block) --------------------------------
__global__ void k_scan() {
    int t = threadIdx.x;
    __shared__ int stot[2][LBL];
    if (t < 16) {
        int side = t >> 3, l = t & 7, s = 0;
        for (int b = 0; b < NBLK; b++) s += g_blockcnt[side][b][l];
        stot[side][l] = s;
    }
    __syncthreads();
    if (t < 2) {
        int run = 0;
        for (int l = 0; l < LBL; l++) {
            int c = stot[t][l];
            g_cnt[t][l] = c;
            g_boffA[t][l] = run;
            run += (c + 63) & ~63;   // 64-aligned bucket storage
        }
        g_boffA[t][LBL] = run;
    }
    __syncthreads();
    if (t < 16) {
        int side = t >> 3, l = t & 7;
        int run = g_boffA[side][l];
        for (int b = 0; b < NBLK; b++) {
            g_base[side][b][l] = run;
            run += g_blockcnt[side][b][l];
        }
    }
}

// ---------------- 3. stable deterministic scatter -------------------------
__global__ void k_scatter(const int* __restrict__ cseg, const int* __restrict__ sseg) {
    int side = blockIdx.y;
    const int* seg = side ? sseg : cseg;
    int t = threadIdx.x, blk = blockIdx.x;
    __shared__ int pre[LBL][256];
    int base = blk * 2048 + t * 8;
    int lab[8];
    int lc[LBL] = {0, 0, 0, 0, 0, 0, 0, 0};
#pragma unroll
    for (int j = 0; j < 8; j++) { lab[j] = seg[base + j] & 7; lc[lab[j]]++; }
#pragma unroll
    for (int l = 0; l < LBL; l++) pre[l][t] = lc[l];
    __syncthreads();
    if (t < LBL) {  // serial exclusive scan per label (deterministic)
        int run = 0;
        for (int i = 0; i < 256; i++) { int v = pre[t][i]; pre[t][i] = run; run += v; }
    }
    __syncthreads();
    int off[LBL];
#pragma unroll
    for (int l = 0; l < LBL; l++) off[l] = g_base[side][blk][l] + pre[l][t];
#pragma unroll
    for (int j = 0; j < 8; j++) {
        int l = lab[j];
        int p = off[l]++;
        int i = base + j;
        g_idx[side][p] = i;
        g_pos[side][i] = p;
    }
}

// ---------------- 3b. zero the alignment gaps in g_packed ------------------
__global__ void k_zerogap() {
    int side = blockIdx.y, l = blockIdx.x, t = threadIdx.x;
    int start = g_boffA[side][l] + g_cnt[side][l];
    int end = g_boffA[side][l + 1];
    for (int ch = 0; ch < C64; ch++)
        for (int p = start + t; p < end; p += 256)
            g_packed[side][ch][p] = 0.f;
}

// ---------------- 4. pack features into bucket order ----------------------
__global__ void k_pack(const float* __restrict__ cont, const float* __restrict__ styl) {
    int side = blockIdx.y;
    const float4* X = (const float4*)(side ? styl : cont);
    int e = blockIdx.x * 256 + threadIdx.x;  // over 64 * 65536 float4 groups
    int c = e >> 16;
    int o4 = e & 65535;
    float4 v = X[(c << 16) + o4];
    int4 p = ((const int4*)g_pos[side])[o4];
    float* P = g_packed[side][c];
    P[p.x] = v.x; P[p.y] = v.y; P[p.z] = v.z; P[p.w] = v.w;
}

// ---------------- 5. raw second moments per (side,label,chunk) ------------
__global__ void k_s2() {
    int side = blockIdx.z, l = blockIdx.y, ck = blockIdx.x, t = threadIdx.x;
    __shared__ __align__(16) float sA[C64][34];   // ch-major, pad 2 (8B-aligned rows)
    __shared__ float ssum[C64][4];
    int b0 = g_boffA[side][l];
    int cnt = g_cnt[side][l];
    int nt = ((cnt + 63) & ~63) >> 5;               // 32-pixel tiles (padded data is 0)
    int t0 = nt * ck / S2CHUNK, t1 = nt * (ck + 1) / S2CHUNK;
    int r0 = (t >> 4) << 2, c0 = (t & 15) << 2;
    unsigned long long acc[4][4];
#pragma unroll
    for (int i = 0; i < 4; i++)
#pragma unroll
        for (int j = 0; j < 4; j++) acc[i][j] = pk2(0.f, 0.f);
    int ch = t >> 2, po = (t & 3) * 8;
    const float* src = g_packed[side][ch];
    float csum = 0.f;

    for (int pb = b0 + t0 * 32; pb < b0 + t1 * 32; pb += 32) {
        // stage 32 pixels x 64 channels (fully aligned, zero-padded)
        float4 a = *(const float4*)&src[pb + po];
        float4 b = *(const float4*)&src[pb + po + 4];
        sA[ch][po + 0] = a.x; sA[ch][po + 1] = a.y;
        sA[ch][po + 2] = a.z; sA[ch][po + 3] = a.w;
        sA[ch][po + 4] = b.x; sA[ch][po + 5] = b.y;
        sA[ch][po + 6] = b.z; sA[ch][po + 7] = b.w;
        csum += a.x + a.y + a.z + a.w + b.x + b.y + b.z + b.w;
        __syncthreads();
#pragma unroll
        for (int pp = 0; pp < 32; pp += 2) {
            unsigned long long ar[4], br[4];
#pragma unroll
            for (int i = 0; i < 4; i++)
                ar[i] = *(const unsigned long long*)&sA[r0 + i][pp];
#pragma unroll
            for (int j = 0; j < 4; j++)
                br[j] = *(const unsigned long long*)&sA[c0 + j][pp];
#pragma unroll
            for (int i = 0; i < 4; i++)
#pragma unroll
                for (int j = 0; j < 4; j++) fma2(acc[i][j], ar[i], br[j]);
        }
        __syncthreads();
    }
    float* dst = g_pS2[side][l][ck];
#pragma unroll
    for (int i = 0; i < 4; i++)
#pragma unroll
        for (int j = 0; j < 4; j++) {
            float2 f = upk(acc[i][j]);
            dst[(r0 + i) * C64 + (c0 + j)] = f.x + f.y;
        }
    ssum[ch][t & 3] = csum;
    __syncthreads();
    if (t < C64) {
        float s = ssum[t][0] + ssum[t][1] + ssum[t][2] + ssum[t][3];
        g_psum[side][l][ck][t] = s;
    }
}

// ---------------- 6. reduce partials -> covariance + mean -----------------
__global__ void k_reduce() {
    int l = blockIdx.x, side = blockIdx.y, t = threadIdx.x;
    __shared__ float smu[C64];
    int n = g_cnt[side][l];
    float nF = (float)n;
    if (t < C64) {
        float s = 0.f;
        for (int ck = 0; ck < S2CHUNK; ck++) s += g_psum[side][l][ck][t];
        float mu = s / fmaxf(nF, 1.f);
        smu[t] = mu;
        g_mu[side][l][t] = mu;
    }
    __syncthreads();
    float div = (n == 1) ? 1e-5f : (nF - 1.f);  // n==0 -> -1, matching ref
#pragma unroll
    for (int i = 0; i < 16; i++) {
        int e = t * 16 + i;
        int r = e >> 6, c = e & 63;
        float s2 = 0.f;
        for (int ck = 0; ck < S2CHUNK; ck++) s2 += g_pS2[side][l][ck][e];
        float cov = (s2 - nF * smu[r] * smu[c]) / div;
        if (side == 0 && r == c) cov += 1.f;
        g_cov[side][l][e] = cov;
    }
}

// ---------------- 7. Newton-Schulz: matrix sqrt / inv-sqrt ----------------
__global__ void k_ns() {
    int l = blockIdx.x, side = blockIdx.y, t = threadIdx.x;
    __shared__ float sY[C64][C64];
    __shared__ float sZ[C64][C64];
    __shared__ float sT[C64][C64];
    const float* A = g_cov[side][l];
#pragma unroll
    for (int i = 0; i < 16; i++) {
        int e = t * 16 + i;
        sY[e >> 6][e & 63] = A[e];
    }
    __syncthreads();
    if (t < C64) {  // Gershgorin row sums (reuse sZ row 0 as scratch)
        float rs = 0.f;
        for (int c = 0; c < C64; c++) rs += fabsf(sY[t][c]);
        sZ[0][t] = rs;
    }
    __syncthreads();
    float s = 0.f;
    for (int i = 0; i < C64; i++) s = fmaxf(s, sZ[0][i]);
    bool zero = (s < 1e-20f);
    if (zero) s = 1.f;
    float inv = 1.f / s;
    __syncthreads();
#pragma unroll
    for (int i = 0; i < 16; i++) {
        int e = t * 16 + i;
        int r = e >> 6, c = e & 63;
        sY[r][c] *= inv;
        sZ[r][c] = (r == c) ? 1.f : 0.f;
    }
    int r0 = (t >> 4) << 2, c0 = (t & 15) << 2;
    for (int it = 0; it < NSIT; it++) {
        __syncthreads();
        float tt[4][4] = {};
        for (int k = 0; k < C64; k++) {
            float zr[4], yc[4];
#pragma unroll
            for (int i = 0; i < 4; i++) zr[i] = sZ[r0 + i][k];
#pragma unroll
            for (int j = 0; j < 4; j++) yc[j] = sY[k][c0 + j];
#pragma unroll
            for (int i = 0; i < 4; i++)
#pragma unroll
                for (int j = 0; j < 4; j++) tt[i][j] = fmaf(zr[i], yc[j], tt[i][j]);
        }
#pragma unroll
        for (int i = 0; i < 4; i++)
#pragma unroll
            for (int j = 0; j < 4; j++) {
                float v = -0.5f * tt[i][j];
                if (r0 + i == c0 + j) v += 1.5f;
                sT[r0 + i][c0 + j] = v;
            }
        __syncthreads();
        float yn[4][4] = {}, zn[4][4] = {};
        for (int k = 0; k < C64; k++) {
            float yr[4], tc[4], tr[4], zc[4];
#pragma unroll
            for (int i = 0; i < 4; i++) { yr[i] = sY[r0 + i][k]; tr[i] = sT[r0 + i][k]; }
#pragma unroll
            for (int j = 0; j < 4; j++) { tc[j] = sT[k][c0 + j]; zc[j] = sZ[k][c0 + j]; }
#pragma unroll
            for (int i = 0; i < 4; i++)
#pragma unroll
                for (int j = 0; j < 4; j++) {
                    yn[i][j] = fmaf(yr[i], tc[j], yn[i][j]);
                    zn[i][j] = fmaf(tr[i], zc[j], zn[i][j]);
                }
        }
        __syncthreads();
#pragma unroll
        for (int i = 0; i < 4; i++)
#pragma unroll
            for (int j = 0; j < 4; j++) {
                sY[r0 + i][c0 + j] = yn[i][j];
                sZ[r0 + i][c0 + j] = zn[i][j];
            }
    }
    __syncthreads();
    float fac = zero ? 0.f : (side == 0 ? (1.f / sqrtf(s)) : sqrtf(s));
    float* M = g_M[side][l];
#pragma unroll
    for (int i = 0; i < 4; i++)
#pragma unroll
        for (int j = 0; j < 4; j++) {
            float v = (side == 0 ? sZ[r0 + i][c0 + j] : sY[r0 + i][c0 + j]) * fac;
            M[(r0 + i) * C64 + (c0 + j)] = v;
        }
}

// ---------------- 8. T = Co @ Wh, bias = mu_s - T mu_c (validity) ---------
__global__ void k_t() {
    int l = blockIdx.x, t = threadIdx.x;
    __shared__ float sW[C64][C64];  // whitening (content)
    __shared__ float sC[C64][C64];  // coloring (style)
#pragma unroll
    for (int i = 0; i < 16; i++) {
        int e = t * 16 + i;
        int r = e >> 6, c = e & 63;
        sW[r][c] = g_M[0][l][e];
        sC[r][c] = g_M[1][l][e];
    }
    __syncthreads();
    float ncF = (float)g_cnt[0][l], nsF = (float)g_cnt[1][l];
    bool valid = (ncF > 10.f) && (nsF > 10.f) && (ncF < 100.f * nsF) && (nsF < 100.f * ncF);
    int r0 = (t >> 4) << 2, c0 = (t & 15) << 2;
    float tt[4][4] = {};
    for (int k = 0; k < C64; k++) {
        float cr[4], wc[4];
#pragma unroll
        for (int i = 0; i < 4; i++) cr[i] = sC[r0 + i][k];
#pragma unroll
        for (int j = 0; j < 4; j++) wc[j] = sW[k][c0 + j];
#pragma unroll
        for (int i = 0; i < 4; i++)
#pragma unroll
            for (int j = 0; j < 4; j++) tt[i][j] = fmaf(cr[i], wc[j], tt[i][j]);
    }
    if (!valid) {
#pragma unroll
        for (int i = 0; i < 4; i++)
#pragma unroll
            for (int j = 0; j < 4; j++) tt[i][j] = (r0 + i == c0 + j) ? 1.f : 0.f;
    }
    __syncthreads();  // all reads of sW done before reuse
#pragma unroll
    for (int i = 0; i < 4; i++)
#pragma unroll
        for (int j = 0; j < 4; j++) {
            sW[r0 + i][c0 + j] = tt[i][j];
            g_T[l][(r0 + i) * C64 + (c0 + j)] = tt[i][j];
        }
    __syncthreads();
    if (t < C64) {
        float b = 0.f;
        for (int c = 0; c < C64; c++) b = fmaf(sW[t][c], g_mu[0][l][c], b);
        g_bias[l][t] = valid ? (g_mu[1][l][t] - b) : 0.f;
    }
}

// ---------------- 9. apply Y = T X + b, scatter to output -----------------
__global__ void k_apply(float* __restrict__ out) {
    int l = blockIdx.y, ck = blockIdx.x, t = threadIdx.x;
    __shared__ __align__(16) float sX[C64][68];   // [channel][pixel]
    __shared__ __align__(16) float sTc[C64][68];  // sTc[c][r] = T[r][c]
    __shared__ float sb[C64];
    int b0 = g_boffA[0][l];
    int cnt = g_cnt[0][l];
    int ae = b0 + cnt;                       // actual end (guard writes)
    int nt = ((cnt + 63) & ~63) >> 6;        // 64-pixel tiles (padded data is 0)
    int t0 = nt * ck / APCHUNK, t1 = nt * (ck + 1) / APCHUNK;
#pragma unroll
    for (int i = 0; i < 16; i++) {
        int e = t * 16 + i;
        sTc[e & 63][e >> 6] = g_T[l][e];
    }
    if (t < C64) sb[t] = g_bias[l][t];
    int tx = t & 15, ty = t >> 4;
    int p0 = tx * 4, r0 = ty * 4;
    int ch = t >> 2, po = (t & 3) * 16;
    const float* src = g_packed[0][ch];
    __syncthreads();

    for (int pb = b0 + t0 * 64; pb < b0 + t1 * 64; pb += 64) {
        // stage 64 pixels x 64 channels (fully aligned, zero-padded)
#pragma unroll
        for (int k = 0; k < 16; k += 4) {
            float4 v = *(const float4*)&src[pb + po + k];
            *(float4*)&sX[ch][po + k] = v;
        }
        __syncthreads();

        unsigned long long a01[4], a23[4];
#pragma unroll
        for (int i = 0; i < 4; i++) { a01[i] = pk2(0.f, 0.f); a23[i] = pk2(0.f, 0.f); }
        for (int c = 0; c < C64; c++) {
            float4 X = *(const float4*)&sX[c][p0];
            unsigned long long x01 = pk2(X.x, X.y), x23 = pk2(X.z, X.w);
            float4 T4 = *(const float4*)&sTc[c][r0];
            unsigned long long t0p = pk2(T4.x, T4.x);
            fma2(a01[0], t0p, x01); fma2(a23[0], t0p, x23);
            unsigned long long t1p = pk2(T4.y, T4.y);
            fma2(a01[1], t1p, x01); fma2(a23[1], t1p, x23);
            unsigned long long t2p = pk2(T4.z, T4.z);
            fma2(a01[2], t2p, x01); fma2(a23[2], t2p, x23);
            unsigned long long t3p = pk2(T4.w, T4.w);
            fma2(a01[3], t3p, x01); fma2(a23[3], t3p, x23);
        }
        int pix[4] = {0, 0, 0, 0};
#pragma unroll
        for (int p = 0; p < 4; p++)
            if (pb + p0 + p < ae) pix[p] = g_idx[0][pb + p0 + p];
#pragma unroll
        for (int i = 0; i < 4; i++) {
            float2 f01 = upk(a01[i]);
            float2 f23 = upk(a23[i]);
            float bb = sb[r0 + i];
            long long rowb = (long long)(r0 + i) * NPIX;
            if (pb + p0 + 0 < ae) out[rowb + pix[0]] = f01.x + bb;
            if (pb + p0 + 1 < ae) out[rowb + pix[1]] = f01.y + bb;
            if (pb + p0 + 2 < ae) out[rowb + pix[2]] = f23.x + bb;
            if (pb + p0 + 3 < ae) out[rowb + pix[3]] = f23.y + bb;
        }
        __syncthreads();
    }
}

// ---------------- launch ---------------------------------------------------
extern "C" void kernel_launch(void* const* d_in, const int* in_sizes, int n_in,
                              void* d_out, int out_size) {
    (void)in_sizes; (void)n_in; (void)out_size;
    const float* cont = (const float*)d_in[0];
    const float* styl = (const float*)d_in[1];
    const int* cseg = (const int*)d_in[2];
    const int* sseg = (const int*)d_in[3];
    float* out = (float*)d_out;

    k_hist<<<dim3(NBLK, 2), 256>>>(cseg, sseg);
    k_scan<<<1, 32>>>();
    k_scatter<<<dim3(NBLK, 2), 256>>>(cseg, sseg);
    k_zerogap<<<dim3(LBL, 2), 256>>>();
    k_pack<<<dim3((C64 * NPIX / 4) / 256, 2), 256>>>(cont, styl);
    k_s2<<<dim3(S2CHUNK, LBL, 2), 256>>>();
    k_reduce<<<dim3(LBL, 2), 256>>>();
    k_ns<<<dim3(LBL, 2), 256>>>();
    k_t<<<LBL, 256>>>();
    k_apply<<<dim3(APCHUNK, LBL), 256>>>(out);
}

// round 10
// speedup vs baseline: 1.3259x; 1.3259x over previous
#include <cuda_runtime.h>
#include <cstdint>

#define NPIX 262144      // 512*512
#define C64  64
#define LBL  8
#define NBLK 128         // hist blocks per side, 2048 px each
#define S2CHUNK 16
#define APCHUNK 32
#define NSIT 5
#define PADPIX (NPIX + 512)
#define APS 268          // apply sX row stride (floats): 268*4 B, 16B-multiple, odd/16 bank step
#define APSMEM (C64 * APS * 4 + C64 * C64 * 8 + 256)

typedef unsigned long long ull;

// ---------------- static device scratch (allocations are forbidden) -------
__device__ int   g_blockcnt[2][NBLK][LBL];
__device__ int   g_base[2][NBLK][LBL];
__device__ int   g_boffA[2][LBL + 1];            // 64-aligned bucket starts
__device__ int   g_cnt[2][LBL];                  // actual bucket sizes
__device__ __align__(16) int   g_idx[2][PADPIX]; // bucket pos -> pixel index
__device__ __align__(16) int   g_pos[2][NPIX];   // pixel index -> bucket pos
__device__ __align__(16) float g_packed[2][C64][PADPIX];
__device__ float g_pS2[2][LBL][S2CHUNK][C64 * C64];
__device__ float g_psum[2][LBL][S2CHUNK][C64];
__device__ float g_mu[2][LBL][C64];
__device__ float g_M[2][LBL][C64 * C64];  // side0: (cov_c+I)^-1/2, side1: cov_s^1/2
__device__ float g_T[LBL][C64 * C64];
__device__ float g_bias[LBL][C64];

// ---------------- packed f32x2 helpers ------------------------------------
__device__ __forceinline__ ull pk2(float lo, float hi) {
    ull r;
    asm("mov.b64 %0, {%1, %2};" : "=l"(r) : "f"(lo), "f"(hi));
    return r;
}
__device__ __forceinline__ void fma2(ull& d, ull a, ull b) {
    asm("fma.rn.f32x2 %0, %1, %2, %0;" : "+l"(d) : "l"(a), "l"(b));
}
__device__ __forceinline__ float2 upk(ull v) {
    float2 f;
    asm("mov.b64 {%0, %1}, %2;" : "=f"(f.x), "=f"(f.y) : "l"(v));
    return f;
}

// ---------------- 1. per-block label histograms ---------------------------
__global__ void k_hist(const int* __restrict__ cseg, const int* __restrict__ sseg) {
    int side = blockIdx.y;
    const int* seg = side ? sseg : cseg;
    int t = threadIdx.x;
    __shared__ int sc[LBL];
    if (t < LBL) sc[t] = 0;
    __syncthreads();
    int base = blockIdx.x * 2048 + t * 8;
    int lc[LBL] = {0, 0, 0, 0, 0, 0, 0, 0};
#pragma unroll
    for (int j = 0; j < 8; j++) { int l = seg[base + j] & 7; lc[l]++; }
#pragma unroll
    for (int l = 0; l < LBL; l++)
        if (lc[l]) atomicAdd(&sc[l], lc[l]);
    __syncthreads();
    if (t < LBL) g_blockcnt[side][blockIdx.x][t] = sc[t];
}

// ---------------- 2. scans (tiny, 1 block) --------------------------------
__global__ void k_scan() {
    int t = threadIdx.x;
    __shared__ int stot[2][LBL];
    if (t < 16) {
        int side = t >> 3, l = t & 7, s = 0;
        for (int b = 0; b < NBLK; b++) s += g_blockcnt[side][b][l];
        stot[side][l] = s;
    }
    __syncthreads();
    if (t < 2) {
        int run = 0;
        for (int l = 0; l < LBL; l++) {
            int c = stot[t][l];
            g_cnt[t][l] = c;
            g_boffA[t][l] = run;
            run += (c + 63) & ~63;   // 64-aligned bucket storage
        }
        g_boffA[t][LBL] = run;
    }
    __syncthreads();
    if (t < 16) {
        int side = t >> 3, l = t & 7;
        int run = g_boffA[side][l];
        for (int b = 0; b < NBLK; b++) {
            g_base[side][b][l] = run;
            run += g_blockcnt[side][b][l];
        }
    }
}

// ---------------- 3. stable deterministic scatter (+ gap zero tail) -------
__global__ void k_scatter(const int* __restrict__ cseg, const int* __restrict__ sseg) {
    int side = blockIdx.y;
    const int* seg = side ? sseg : cseg;
    int t = threadIdx.x, blk = blockIdx.x;
    __shared__ int pre[LBL][256];
    int base = blk * 2048 + t * 8;
    int lab[8];
    int lc[LBL] = {0, 0, 0, 0, 0, 0, 0, 0};
#pragma unroll
    for (int j = 0; j < 8; j++) { lab[j] = seg[base + j] & 7; lc[lab[j]]++; }
#pragma unroll
    for (int l = 0; l < LBL; l++) pre[l][t] = lc[l];
    __syncthreads();
    if (t < LBL) {  // serial exclusive scan per label (deterministic)
        int run = 0;
        for (int i = 0; i < 256; i++) { int v = pre[t][i]; pre[t][i] = run; run += v; }
    }
    __syncthreads();
    int off[LBL];
#pragma unroll
    for (int l = 0; l < LBL; l++) off[l] = g_base[side][blk][l] + pre[l][t];
#pragma unroll
    for (int j = 0; j < 8; j++) {
        int l = lab[j];
        int p = off[l]++;
        int i = base + j;
        g_idx[side][p] = i;
        g_pos[side][i] = p;
    }
    // ---- fold in zeroing of bucket alignment gaps (blocks 0..7 only) ----
    if (blk < LBL) {
        int l = blk;
        int start = g_boffA[side][l] + g_cnt[side][l];
        int gap = g_boffA[side][l + 1] - start;
        int ch = t >> 2;
        for (int p = (t & 3); p < gap; p += 4)
            g_packed[side][ch][start + p] = 0.f;
    }
}

// ---------------- 4. pack features into bucket order ----------------------
__global__ void k_pack(const float* __restrict__ cont, const float* __restrict__ styl) {
    int side = blockIdx.y;
    const float4* X = (const float4*)(side ? styl : cont);
    int e = blockIdx.x * 256 + threadIdx.x;  // over 64 * 65536 float4 groups
    int c = e >> 16;
    int o4 = e & 65535;
    float4 v = X[(c << 16) + o4];
    int4 p = ((const int4*)g_pos[side])[o4];
    float* P = g_packed[side][c];
    P[p.x] = v.x; P[p.y] = v.y; P[p.z] = v.z; P[p.w] = v.w;
}

// ---------------- 5. raw second moments per (side,label,chunk) ------------
// thread tile: r = 4*rg + i (rg=t>>4, broadcast within half-warp),
//              c = c_low + 16*j (c_low=t&15, conflict-free strided banks)
__global__ void k_s2() {
    int side = blockIdx.z, l = blockIdx.y, ck = blockIdx.x, t = threadIdx.x;
    __shared__ __align__(16) float sA[C64][66];   // stride 66: bank step 2 per c
    __shared__ float ssum[C64][4];
    int b0 = g_boffA[side][l];
    int cnt = g_cnt[side][l];
    int nt = (cnt + 63) >> 6;                     // 64-pixel tiles (zero-padded)
    int t0 = nt * ck / S2CHUNK, t1 = nt * (ck + 1) / S2CHUNK;
    int c_low = t & 15, rg = t >> 4;
    ull acc[4][4];
#pragma unroll
    for (int i = 0; i < 4; i++)
#pragma unroll
        for (int j = 0; j < 4; j++) acc[i][j] = pk2(0.f, 0.f);
    int ch = t >> 2, po = (t & 3) * 16;
    const float* src = g_packed[side][ch];
    float csum = 0.f;

    for (int pb = b0 + t0 * 64; pb < b0 + t1 * 64; pb += 64) {
        // stage 64 pixels x 64 channels (aligned, zero-padded)
#pragma unroll
        for (int k = 0; k < 16; k += 4) {
            float4 v = *(const float4*)&src[pb + po + k];
            sA[ch][po + k + 0] = v.x; sA[ch][po + k + 1] = v.y;
            sA[ch][po + k + 2] = v.z; sA[ch][po + k + 3] = v.w;
            csum += v.x + v.y + v.z + v.w;
        }
        __syncthreads();
#pragma unroll 8
        for (int pp = 0; pp < 64; pp += 2) {
            ull ar[4], br[4];
#pragma unroll
            for (int i = 0; i < 4; i++)
                ar[i] = *(const ull*)&sA[4 * rg + i][pp];
#pragma unroll
            for (int j = 0; j < 4; j++)
                br[j] = *(const ull*)&sA[c_low + 16 * j][pp];
#pragma unroll
            for (int i = 0; i < 4; i++)
#pragma unroll
                for (int j = 0; j < 4; j++) fma2(acc[i][j], ar[i], br[j]);
        }
        __syncthreads();
    }
    float* dst = g_pS2[side][l][ck];
#pragma unroll
    for (int i = 0; i < 4; i++)
#pragma unroll
        for (int j = 0; j < 4; j++) {
            float2 f = upk(acc[i][j]);
            dst[(4 * rg + i) * C64 + (c_low + 16 * j)] = f.x + f.y;
        }
    ssum[ch][t & 3] = csum;
    __syncthreads();
    if (t < C64) {
        float s = ssum[t][0] + ssum[t][1] + ssum[t][2] + ssum[t][3];
        g_psum[side][l][ck][t] = s;
    }
}

// ---------------- 6. reduce + Newton-Schulz sqrt/inv-sqrt (merged) --------
__global__ void k_ns() {
    int l = blockIdx.x, side = blockIdx.y, t = threadIdx.x;
    __shared__ float sY[C64][C64];
    __shared__ float sZ[C64][C64];
    __shared__ float sT[C64][C64];
    int n = g_cnt[side][l];
    float nF = (float)n;
    if (t < C64) {  // mean from partial sums (sT row0 as scratch)
        float s = 0.f;
        for (int ck = 0; ck < S2CHUNK; ck++) s += g_psum[side][l][ck][t];
        float mu = s / fmaxf(nF, 1.f);
        sT[0][t] = mu;
        g_mu[side][l][t] = mu;
    }
    __syncthreads();
    float div = (n == 1) ? 1e-5f : (nF - 1.f);  // n==0 -> -1, matching ref
#pragma unroll
    for (int i = 0; i < 16; i++) {
        int e = t * 16 + i;
        int r = e >> 6, c = e & 63;
        float s2 = 0.f;
        for (int ck = 0; ck < S2CHUNK; ck++) s2 += g_pS2[side][l][ck][e];
        float cov = (s2 - nF * sT[0][r] * sT[0][c]) / div;
        if (side == 0 && r == c) cov += 1.f;
        sY[r][c] = cov;
    }
    __syncthreads();
    if (t < C64) {  // Gershgorin row sums (sZ row 0 as scratch)
        float rs = 0.f;
        for (int c = 0; c < C64; c++) rs += fabsf(sY[t][c]);
        sZ[0][t] = rs;
    }
    __syncthreads();
    float s = 0.f;
    for (int i = 0; i < C64; i++) s = fmaxf(s, sZ[0][i]);
    bool zero = (s < 1e-20f);
    if (zero) s = 1.f;
    float inv = 1.f / s;
    __syncthreads();
#pragma unroll
    for (int i = 0; i < 16; i++) {
        int e = t * 16 + i;
        int r = e >> 6, c = e & 63;
        sY[r][c] *= inv;
        sZ[r][c] = (r == c) ? 1.f : 0.f;
    }
    int r0 = (t >> 4) << 2, c0 = (t & 15) << 2;
    for (int it = 0; it < NSIT; it++) {
        __syncthreads();
        float tt[4][4] = {};
        for (int k = 0; k < C64; k++) {
            float zr[4], yc[4];
#pragma unroll
            for (int i = 0; i < 4; i++) zr[i] = sZ[r0 + i][k];
#pragma unroll
            for (int j = 0; j < 4; j++) yc[j] = sY[k][c0 + j];
#pragma unroll
            for (int i = 0; i < 4; i++)
#pragma unroll
                for (int j = 0; j < 4; j++) tt[i][j] = fmaf(zr[i], yc[j], tt[i][j]);
        }
#pragma unroll
        for (int i = 0; i < 4; i++)
#pragma unroll
            for (int j = 0; j < 4; j++) {
                float v = -0.5f * tt[i][j];
                if (r0 + i == c0 + j) v += 1.5f;
                sT[r0 + i][c0 + j] = v;
            }
        __syncthreads();
        float yn[4][4] = {}, zn[4][4] = {};
        for (int k = 0; k < C64; k++) {
            float yr[4], tc[4], tr[4], zc[4];
#pragma unroll
            for (int i = 0; i < 4; i++) { yr[i] = sY[r0 + i][k]; tr[i] = sT[r0 + i][k]; }
#pragma unroll
            for (int j = 0; j < 4; j++) { tc[j] = sT[k][c0 + j]; zc[j] = sZ[k][c0 + j]; }
#pragma unroll
            for (int i = 0; i < 4; i++)
#pragma unroll
                for (int j = 0; j < 4; j++) {
                    yn[i][j] = fmaf(yr[i], tc[j], yn[i][j]);
                    zn[i][j] = fmaf(tr[i], zc[j], zn[i][j]);
                }
        }
        __syncthreads();
#pragma unroll
        for (int i = 0; i < 4; i++)
#pragma unroll
            for (int j = 0; j < 4; j++) {
                sY[r0 + i][c0 + j] = yn[i][j];
                sZ[r0 + i][c0 + j] = zn[i][j];
            }
    }
    __syncthreads();
    float fac = zero ? 0.f : (side == 0 ? (1.f / sqrtf(s)) : sqrtf(s));
    float* M = g_M[side][l];
#pragma unroll
    for (int i = 0; i < 4; i++)
#pragma unroll
        for (int j = 0; j < 4; j++) {
            float v = (side == 0 ? sZ[r0 + i][c0 + j] : sY[r0 + i][c0 + j]) * fac;
            M[(r0 + i) * C64 + (c0 + j)] = v;
        }
}

// ---------------- 7. T = Co @ Wh, bias = mu_s - T mu_c (validity) ---------
__global__ void k_t() {
    int l = blockIdx.x, t = threadIdx.x;
    __shared__ float sW[C64][C64];  // whitening (content)
    __shared__ float sC[C64][C64];  // coloring (style)
#pragma unroll
    for (int i = 0; i < 16; i++) {
        int e = t * 16 + i;
        int r = e >> 6, c = e & 63;
        sW[r][c] = g_M[0][l][e];
        sC[r][c] = g_M[1][l][e];
    }
    __syncthreads();
    float ncF = (float)g_cnt[0][l], nsF = (float)g_cnt[1][l];
    bool valid = (ncF > 10.f) && (nsF > 10.f) && (ncF < 100.f * nsF) && (nsF < 100.f * ncF);
    int r0 = (t >> 4) << 2, c0 = (t & 15) << 2;
    float tt[4][4] = {};
    for (int k = 0; k < C64; k++) {
        float cr[4], wc[4];
#pragma unroll
        for (int i = 0; i < 4; i++) cr[i] = sC[r0 + i][k];
#pragma unroll
        for (int j = 0; j < 4; j++) wc[j] = sW[k][c0 + j];
#pragma unroll
        for (int i = 0; i < 4; i++)
#pragma unroll
            for (int j = 0; j < 4; j++) tt[i][j] = fmaf(cr[i], wc[j], tt[i][j]);
    }
    if (!valid) {
#pragma unroll
        for (int i = 0; i < 4; i++)
#pragma unroll
            for (int j = 0; j < 4; j++) tt[i][j] = (r0 + i == c0 + j) ? 1.f : 0.f;
    }
    __syncthreads();  // all reads of sW done before reuse
#pragma unroll
    for (int i = 0; i < 4; i++)
#pragma unroll
        for (int j = 0; j < 4; j++) {
            sW[r0 + i][c0 + j] = tt[i][j];
            g_T[l][(r0 + i) * C64 + (c0 + j)] = tt[i][j];
        }
    __syncthreads();
    if (t < C64) {
        float b = 0.f;
        for (int c = 0; c < C64; c++) b = fmaf(sW[t][c], g_mu[0][l][c], b);
        g_bias[l][t] = valid ? (g_mu[1][l][t] - b) : 0.f;
    }
}

// ---------------- 8. apply Y = T X + b, scatter to output -----------------
// 256-px tiles, dynamic smem. Thread: r = 4*ty+i (ty=t>>4), pixel pairs
// (2*tx+32m, 2*tx+32m+1) m=0..7 (tx=t&15). T pre-duplicated as u64 pairs.
__global__ void k_apply(float* __restrict__ out) {
    extern __shared__ __align__(16) char apbuf[];
    float (*sX)[APS] = (float(*)[APS])apbuf;
    ull (*sTd)[C64] = (ull(*)[C64])(apbuf + C64 * APS * 4);
    float* sb = (float*)(apbuf + C64 * APS * 4 + C64 * C64 * 8);

    int l = blockIdx.y, ck = blockIdx.x, t = threadIdx.x;
    int b0 = g_boffA[0][l];
    int cnt = g_cnt[0][l];
    int ae = b0 + cnt;                       // actual end (guard writes)
    int nt = (cnt + 255) >> 8;               // 256-pixel tiles
    int t0 = nt * ck / APCHUNK, t1 = nt * (ck + 1) / APCHUNK;

#pragma unroll
    for (int i = 0; i < 16; i++) {           // build duplicated T
        int e = t * 16 + i;
        float v = g_T[l][e];
        sTd[e & 63][e >> 6] = pk2(v, v);
    }
    if (t < C64) sb[t] = g_bias[l][t];
    int tx = t & 15, ty = t >> 4;
    __syncthreads();

    for (int pb = b0 + t0 * 256; pb < b0 + t1 * 256; pb += 256) {
        // stage 256 px x 64 ch: thread covers 2 rows, 8 coalesced float4 each
#pragma unroll
        for (int half = 0; half < 2; half++) {
            int ch = (t >> 3) + (half << 5);
            const float* src = g_packed[0][ch];
            float* drow = sX[ch];
            int po = (t & 7) * 4;
#pragma unroll
            for (int k = 0; k < 8; k++) {
                float4 v = *(const float4*)&src[pb + po + 32 * k];
                *(float4*)&drow[po + 32 * k] = v;
            }
        }
        __syncthreads();

        ull acc[4][8];
#pragma unroll
        for (int i = 0; i < 4; i++)
#pragma unroll
            for (int m = 0; m < 8; m++) acc[i][m] = pk2(0.f, 0.f);
#pragma unroll 4
        for (int c = 0; c < C64; c++) {
            const float* xr = sX[c];
            ull xm[8];
#pragma unroll
            for (int m = 0; m < 8; m++) xm[m] = *(const ull*)&xr[2 * tx + 32 * m];
            ull td[4];
#pragma unroll
            for (int i = 0; i < 4; i++) td[i] = sTd[c][4 * ty + i];
#pragma unroll
            for (int i = 0; i < 4; i++)
#pragma unroll
                for (int m = 0; m < 8; m++) fma2(acc[i][m], td[i], xm[m]);
        }
#pragma unroll
        for (int m = 0; m < 8; m++) {
            int p0 = pb + 2 * tx + 32 * m;
            bool v0 = p0 < ae, v1 = p0 + 1 < ae;
            int i0 = v0 ? g_idx[0][p0] : 0;
            int i1 = v1 ? g_idx[0][p0 + 1] : 0;
#pragma unroll
            for (int i = 0; i < 4; i++) {
                float2 f = upk(acc[i][m]);
                int r = 4 * ty + i;
                float bb = sb[r];
                long long rowb = (long long)r * NPIX;
                if (v0) out[rowb + i0] = f.x + bb;
                if (v1) out[rowb + i1] = f.y + bb;
            }
        }
        __syncthreads();
    }
}

// ---------------- launch ---------------------------------------------------
extern "C" void kernel_launch(void* const* d_in, const int* in_sizes, int n_in,
                              void* d_out, int out_size) {
    (void)in_sizes; (void)n_in; (void)out_size;
    const float* cont = (const float*)d_in[0];
    const float* styl = (const float*)d_in[1];
    const int* cseg = (const int*)d_in[2];
    const int* sseg = (const int*)d_in[3];
    float* out = (float*)d_out;

    cudaFuncSetAttribute(k_apply, cudaFuncAttributeMaxDynamicSharedMemorySize, APSMEM);

    k_hist<<<dim3(NBLK, 2), 256>>>(cseg, sseg);
    k_scan<<<1, 32>>>();
    k_scatter<<<dim3(NBLK, 2), 256>>>(cseg, sseg);
    k_pack<<<dim3((C64 * NPIX / 4) / 256, 2), 256>>>(cont, styl);
    k_s2<<<dim3(S2CHUNK, LBL, 2), 256>>>();
    k_ns<<<dim3(LBL, 2), 256>>>();
    k_t<<<LBL, 256>>>();
    k_apply<<<dim3(APCHUNK, LBL), 256, APSMEM>>>(out);
}